// round 8
// baseline (speedup 1.0000x reference)
#include <cuda_runtime.h>
#include <cstdint>
#include <cstddef>

// Problem constants
#define B_   4
#define L_   4096
#define D_   2048
#define DF_  8192
#define KCAP 2048              // L * 0.5
#define BK   (B_ * KCAP)       // 8192 selected rows total

// ---------------------------------------------------------------------------
// Device scratch (static globals: allocation-free per harness rules)
// ---------------------------------------------------------------------------
__device__ float g_scores[B_ * L_];
__device__ float g_thr[B_];
__device__ int   g_cnt[B_];
__device__ int   g_idx[BK];
__device__ float g_xsel[(size_t)BK * D_];    //  64 MB (tf32-rounded)
__device__ float g_h   [(size_t)BK * DF_];   // 256 MB (tf32-rounded)
__device__ float g_w1t [(size_t)DF_ * D_];   //  64 MB (W1^T K-major, tf32-rounded)
__device__ float g_w2t [(size_t)D_ * DF_];   //  64 MB (W2^T K-major, tf32-rounded)

// ---------------------------------------------------------------------------
// Helpers
// ---------------------------------------------------------------------------
__device__ __forceinline__ uint32_t cvta_smem(const void* p) {
    uint32_t a;
    asm("{ .reg .u64 t; cvta.to.shared.u64 t, %1; cvt.u32.u64 %0, t; }"
        : "=r"(a) : "l"(p));
    return a;
}

__device__ __forceinline__ float to_tf32(float x) {
    uint32_t u;
    asm("cvt.rna.tf32.f32 %0, %1;" : "=r"(u) : "f"(x));
    return __uint_as_float(u);
}

__device__ __forceinline__ float gelu_tanh(float x) {
    float x3 = x * x * x;
    float t  = tanhf(0.7978845608028654f * (x + 0.044715f * x3));
    return 0.5f * x * (1.0f + t);
}

__device__ __forceinline__ void mma1688(float* d, const uint32_t* a, const uint32_t* b) {
    asm volatile(
        "mma.sync.aligned.m16n8k8.row.col.f32.tf32.tf32.f32 "
        "{%0,%1,%2,%3}, {%4,%5,%6,%7}, {%8,%9}, {%0,%1,%2,%3};"
        : "+f"(d[0]), "+f"(d[1]), "+f"(d[2]), "+f"(d[3])
        : "r"(a[0]), "r"(a[1]), "r"(a[2]), "r"(a[3]), "r"(b[0]), "r"(b[1]));
}

// ---------------------------------------------------------------------------
// Kernel 0: zero d_out
// ---------------------------------------------------------------------------
__global__ void k_zero(float4* p, size_t n4) {
    size_t i = (size_t)blockIdx.x * blockDim.x + threadIdx.x;
    size_t stride = (size_t)gridDim.x * blockDim.x;
    float4 z = make_float4(0.f, 0.f, 0.f, 0.f);
    for (; i < n4; i += stride) p[i] = z;
}

// ---------------------------------------------------------------------------
// Kernel 1: router scores (exact fp32) — one warp per token
// ---------------------------------------------------------------------------
__global__ void k_router(const float* __restrict__ x, const float* __restrict__ wr,
                         const float* __restrict__ br) {
    int gw   = (blockIdx.x * blockDim.x + threadIdx.x) >> 5;
    int lane = threadIdx.x & 31;
    if (gw >= B_ * L_) return;
    const float4* row = (const float4*)(x + (size_t)gw * D_);
    const float4* w   = (const float4*)wr;
    float acc = 0.f;
    #pragma unroll 4
    for (int i = lane; i < D_ / 4; i += 32) {
        float4 a = row[i], b = w[i];
        acc += a.x * b.x + a.y * b.y + a.z * b.z + a.w * b.w;
    }
    #pragma unroll
    for (int o = 16; o; o >>= 1) acc += __shfl_xor_sync(0xffffffff, acc, o);
    if (lane == 0) g_scores[gw] = acc + br[0];
}

// ---------------------------------------------------------------------------
// Kernel 2: per-batch k-th-largest threshold via SMEM bitonic sort
// ---------------------------------------------------------------------------
__global__ void k_topk() {
    __shared__ float s[L_];
    int b = blockIdx.x, tid = threadIdx.x;
    for (int i = tid; i < L_; i += blockDim.x) s[i] = g_scores[b * L_ + i];
    __syncthreads();
    for (int size = 2; size <= L_; size <<= 1) {
        for (int stride = size >> 1; stride > 0; stride >>= 1) {
            for (int t = tid; t < L_; t += blockDim.x) {
                int p = t ^ stride;
                if (p > t) {
                    bool up = ((t & size) == 0);
                    float a = s[t], c = s[p];
                    if (up ? (a > c) : (a < c)) { s[t] = c; s[p] = a; }
                }
            }
            __syncthreads();
        }
    }
    if (tid == 0) { g_thr[b] = s[L_ - KCAP]; g_cnt[b] = 0; }
}

// ---------------------------------------------------------------------------
// Kernels 3/4: compact selected-index list (order irrelevant for correctness)
// ---------------------------------------------------------------------------
__global__ void k_sel_gt() {
    int i = blockIdx.x * blockDim.x + threadIdx.x;
    if (i >= B_ * L_) return;
    int b = i >> 12;
    if (g_scores[i] > g_thr[b]) {
        int p = atomicAdd(&g_cnt[b], 1);
        g_idx[b * KCAP + p] = i & (L_ - 1);
    }
}
__global__ void k_sel_eq() {
    int i = blockIdx.x * blockDim.x + threadIdx.x;
    if (i >= B_ * L_) return;
    int b = i >> 12;
    if (g_scores[i] == g_thr[b]) {
        int p = atomicAdd(&g_cnt[b], 1);
        if (p < KCAP) g_idx[b * KCAP + p] = i & (L_ - 1);
    }
}

// ---------------------------------------------------------------------------
// Kernel 5: gather selected tokens (+ RNA tf32 rounding for the GEMM)
// ---------------------------------------------------------------------------
__global__ void k_gather(const float* __restrict__ x) {
    int r   = blockIdx.x;
    int b   = r >> 11;
    int tok = g_idx[r];
    const float4* src = (const float4*)(x + ((size_t)(b * L_ + tok)) * D_);
    float4*       dst = (float4*)(g_xsel + (size_t)r * D_);
    for (int i = threadIdx.x; i < D_ / 4; i += blockDim.x) {
        float4 v = src[i];
        v.x = to_tf32(v.x); v.y = to_tf32(v.y); v.z = to_tf32(v.z); v.w = to_tf32(v.w);
        dst[i] = v;
    }
}

// ---------------------------------------------------------------------------
// Kernel 6: transpose weights to K-major (+ RNA tf32 rounding)
// ---------------------------------------------------------------------------
__global__ void k_transpose(const float* __restrict__ src, int R, int C, int which) {
    __shared__ float t[32][33];
    float* dst = which ? g_w2t : g_w1t;
    int c0 = blockIdx.x * 32, r0 = blockIdx.y * 32;
    for (int j = threadIdx.y; j < 32; j += 8)
        t[j][threadIdx.x] = src[(size_t)(r0 + j) * C + c0 + threadIdx.x];
    __syncthreads();
    for (int j = threadIdx.y; j < 32; j += 8)
        dst[(size_t)(c0 + j) * R + r0 + threadIdx.x] = to_tf32(t[threadIdx.x][j]);
}

// ---------------------------------------------------------------------------
// Kernel 7: tf32 mma.sync GEMM   C[M,N] = A[M,K] * Bt[N,K]^T   (+bias epilogue)
//   mode 0: A=g_xsel, Bt=g_w1t, epilogue gelu -> g_h (tf32-rounded)
//   mode 1: A=g_h,    Bt=g_w2t, epilogue bias -> scatter to out via g_idx
// CTA 128x128x32, 128 threads, 4 warps (2x2) each computing 64x64.
// cp.async double-buffered. SMEM rows padded to 144B (bank-conflict-free LDS).
// ---------------------------------------------------------------------------
#define TK 32
#define SROW 36                      // floats per SMEM row (32 data + 4 pad)
#define A_BYTES (128 * SROW * 4)     // 18432
#define STAGE_BYTES (2 * A_BYTES)    // 36864 (A then B)
#define SM_TOTAL (2 * STAGE_BYTES)   // 73728

__device__ __forceinline__ void prefetch_stage(
    uint32_t sb, int stage, const float* __restrict__ A, const float* __restrict__ Bt,
    size_t rowA0, size_t rowB0, int Ktot, int k0, int tid)
{
    uint32_t base = sb + stage * STAGE_BYTES;
    #pragma unroll
    for (int j = 0; j < 8; j++) {
        int c = j * 128 + tid;
        int r = c >> 3, q = c & 7;
        const float* ga = A  + (rowA0 + (size_t)r) * (size_t)Ktot + k0 + q * 4;
        const float* gb = Bt + (rowB0 + (size_t)r) * (size_t)Ktot + k0 + q * 4;
        uint32_t sa = base + (uint32_t)(r * 144 + q * 16);
        uint32_t sbb = sa + A_BYTES;
        asm volatile("cp.async.cg.shared.global [%0], [%1], 16;" :: "r"(sa),  "l"(ga) : "memory");
        asm volatile("cp.async.cg.shared.global [%0], [%1], 16;" :: "r"(sbb), "l"(gb) : "memory");
    }
}

__global__ __launch_bounds__(128) void k_gemm(
    const float* __restrict__ bias, float* __restrict__ out,
    int Ktot, int Ntot, int mode)
{
    extern __shared__ char smem[];
    uint32_t sb = cvta_smem(smem);
    int tid  = threadIdx.x;
    int wid  = tid >> 5;
    int lane = tid & 31;
    int wm   = wid & 1;                       // warp M index (0/1)
    int wn   = wid >> 1;                      // warp N index (0/1)

    const float* A  = (mode == 0) ? g_xsel : g_h;
    const float* Bt = (mode == 0) ? g_w1t  : g_w2t;

    const size_t rowA0 = (size_t)blockIdx.y * 128;
    const size_t colB0 = (size_t)blockIdx.x * 128;
    const int NS = Ktot / TK;

    float acc[4][8][4];
    #pragma unroll
    for (int mi = 0; mi < 4; mi++)
        #pragma unroll
        for (int ni = 0; ni < 8; ni++)
            #pragma unroll
            for (int j = 0; j < 4; j++) acc[mi][ni][j] = 0.f;

    // prologue: stages 0, 1
    prefetch_stage(sb, 0, A, Bt, rowA0, colB0, Ktot, 0, tid);
    asm volatile("cp.async.commit_group;" ::: "memory");
    prefetch_stage(sb, 1, A, Bt, rowA0, colB0, Ktot, TK, tid);
    asm volatile("cp.async.commit_group;" ::: "memory");

    const int lr = lane >> 2;   // 0..7
    const int lc = lane & 3;    // 0..3

    for (int s = 0; s < NS; s++) {
        asm volatile("cp.async.wait_group 1;" ::: "memory");
        __syncthreads();

        const float* sA = (const float*)(smem + (s & 1) * STAGE_BYTES);
        const float* sB = (const float*)(smem + (s & 1) * STAGE_BYTES + A_BYTES);

        #pragma unroll
        for (int ks = 0; ks < 4; ks++) {
            int kb = ks * 8;
            uint32_t afr[4][4];
            uint32_t bfr[8][2];
            #pragma unroll
            for (int mi = 0; mi < 4; mi++) {
                int r = wm * 64 + mi * 16 + lr;
                int c = kb + lc;
                afr[mi][0] = __float_as_uint(sA[r * SROW + c]);
                afr[mi][1] = __float_as_uint(sA[(r + 8) * SROW + c]);
                afr[mi][2] = __float_as_uint(sA[r * SROW + c + 4]);
                afr[mi][3] = __float_as_uint(sA[(r + 8) * SROW + c + 4]);
            }
            #pragma unroll
            for (int ni = 0; ni < 8; ni++) {
                int n = wn * 64 + ni * 8 + lr;
                bfr[ni][0] = __float_as_uint(sB[n * SROW + kb + lc]);
                bfr[ni][1] = __float_as_uint(sB[n * SROW + kb + 4 + lc]);
            }
            #pragma unroll
            for (int mi = 0; mi < 4; mi++)
                #pragma unroll
                for (int ni = 0; ni < 8; ni++)
                    mma1688(acc[mi][ni], afr[mi], bfr[ni]);
        }

        __syncthreads();   // everyone done reading buf (s&1) before refill
        if (s + 2 < NS)
            prefetch_stage(sb, s & 1, A, Bt, rowA0, colB0, Ktot, (s + 2) * TK, tid);
        asm volatile("cp.async.commit_group;" ::: "memory");
    }

    // ------------------------- epilogue -------------------------
    // accum layout m16n8: c0/c1 at (row lr, col 2*lc / 2*lc+1), c2/c3 at row lr+8
    #pragma unroll
    for (int mi = 0; mi < 4; mi++) {
        size_t m0 = rowA0 + (size_t)(wm * 64 + mi * 16 + lr);
        size_t m1 = m0 + 8;
        if (mode == 0) {
            float* row0 = g_h + m0 * (size_t)Ntot;
            float* row1 = g_h + m1 * (size_t)Ntot;
            #pragma unroll
            for (int ni = 0; ni < 8; ni++) {
                size_t col = colB0 + wn * 64 + ni * 8 + lc * 2;
                float b0 = bias[col], b1 = bias[col + 1];
                float2 v0, v1;
                v0.x = to_tf32(gelu_tanh(acc[mi][ni][0] + b0));
                v0.y = to_tf32(gelu_tanh(acc[mi][ni][1] + b1));
                v1.x = to_tf32(gelu_tanh(acc[mi][ni][2] + b0));
                v1.y = to_tf32(gelu_tanh(acc[mi][ni][3] + b1));
                *(float2*)(row0 + col) = v0;
                *(float2*)(row1 + col) = v1;
            }
        } else {
            int tok0 = g_idx[m0], tok1 = g_idx[m1];
            int b0i = (int)(m0 >> 11), b1i = (int)(m1 >> 11);
            float* row0 = out + ((size_t)(b0i * L_ + tok0)) * D_;
            float* row1 = out + ((size_t)(b1i * L_ + tok1)) * D_;
            #pragma unroll
            for (int ni = 0; ni < 8; ni++) {
                size_t col = colB0 + wn * 64 + ni * 8 + lc * 2;
                float b0 = bias[col], b1 = bias[col + 1];
                float2 v0, v1;
                v0.x = acc[mi][ni][0] + b0;
                v0.y = acc[mi][ni][1] + b1;
                v1.x = acc[mi][ni][2] + b0;
                v1.y = acc[mi][ni][3] + b1;
                *(float2*)(row0 + col) = v0;
                *(float2*)(row1 + col) = v1;
            }
        }
    }
}

// ---------------------------------------------------------------------------
// Host entry
// ---------------------------------------------------------------------------
extern "C" void kernel_launch(void* const* d_in, const int* in_sizes, int n_in,
                              void* d_out, int out_size) {
    (void)in_sizes; (void)n_in;
    const float* x  = (const float*)d_in[0];
    const float* wr = (const float*)d_in[1];
    const float* br = (const float*)d_in[2];
    const float* w1 = (const float*)d_in[3];
    const float* b1 = (const float*)d_in[4];
    const float* w2 = (const float*)d_in[5];
    const float* b2 = (const float*)d_in[6];
    float* out = (float*)d_out;

    // 0) zero output (poisoned by harness)
    k_zero<<<2048, 256>>>((float4*)out, (size_t)out_size / 4);

    // 1) router scores (fp32 exact)
    k_router<<<(B_ * L_ * 32) / 256, 256>>>(x, wr, br);

    // 2) per-batch threshold + counter reset
    k_topk<<<B_, 1024>>>();

    // 3/4) selection -> compact index list
    k_sel_gt<<<(B_ * L_) / 256, 256>>>();
    k_sel_eq<<<(B_ * L_) / 256, 256>>>();

    // 5) gather selected tokens (tf32-rounded)
    k_gather<<<BK, 256>>>(x);

    // 6) transpose weights to K-major (tf32-rounded)
    dim3 tb(32, 8);
    k_transpose<<<dim3(DF_ / 32, D_ / 32), tb>>>(w1, D_, DF_, 0);   // -> g_w1t [DF,D]
    k_transpose<<<dim3(D_ / 32, DF_ / 32), tb>>>(w2, DF_, D_, 1);   // -> g_w2t [D,DF]

    // 7) FFN GEMMs (mma.sync tf32)
    static int smem_set = 0;
    if (!smem_set) {
        cudaFuncSetAttribute(k_gemm, cudaFuncAttributeMaxDynamicSharedMemorySize, SM_TOTAL);
        smem_set = 1;
    }
    k_gemm<<<dim3(DF_ / 128, BK / 128), 128, SM_TOTAL>>>(b1, out, D_,  DF_, 0);
    k_gemm<<<dim3(D_  / 128, BK / 128), 128, SM_TOTAL>>>(b2, out, DF_, D_,  1);
}

// round 9
// speedup vs baseline: 1.0466x; 1.0466x over previous
#include <cuda_runtime.h>
#include <cstdint>
#include <cstddef>

// Problem constants
#define B_   4
#define L_   4096
#define D_   2048
#define DF_  8192
#define KCAP 2048              // L * 0.5
#define BK   (B_ * KCAP)       // 8192 selected rows total

// ---------------------------------------------------------------------------
// Device scratch (static globals: allocation-free per harness rules)
// ---------------------------------------------------------------------------
__device__ float g_scores[B_ * L_];
__device__ float g_thr[B_];
__device__ int   g_cnt[B_];
__device__ int   g_idx[BK];
__device__ float g_xsel[(size_t)BK * D_];    //  64 MB (tf32-rounded)
__device__ float g_h   [(size_t)BK * DF_];   // 256 MB (tf32-rounded)
__device__ float g_w1t [(size_t)DF_ * D_];   //  64 MB (W1^T K-major, tf32-rounded)
__device__ float g_w2t [(size_t)D_ * DF_];   //  64 MB (W2^T K-major, tf32-rounded)

// ---------------------------------------------------------------------------
// Helpers
// ---------------------------------------------------------------------------
__device__ __forceinline__ uint32_t cvta_smem(const void* p) {
    uint32_t a;
    asm("{ .reg .u64 t; cvta.to.shared.u64 t, %1; cvt.u32.u64 %0, t; }"
        : "=r"(a) : "l"(p));
    return a;
}

__device__ __forceinline__ float to_tf32(float x) {
    uint32_t u;
    asm("cvt.rna.tf32.f32 %0, %1;" : "=r"(u) : "f"(x));
    return __uint_as_float(u);
}

__device__ __forceinline__ float gelu_tanh(float x) {
    float x3 = x * x * x;
    float t  = tanhf(0.7978845608028654f * (x + 0.044715f * x3));
    return 0.5f * x * (1.0f + t);
}

__device__ __forceinline__ void mma1688(float* d, const uint32_t* a, const uint32_t* b) {
    asm volatile(
        "mma.sync.aligned.m16n8k8.row.col.f32.tf32.tf32.f32 "
        "{%0,%1,%2,%3}, {%4,%5,%6,%7}, {%8,%9}, {%0,%1,%2,%3};"
        : "+f"(d[0]), "+f"(d[1]), "+f"(d[2]), "+f"(d[3])
        : "r"(a[0]), "r"(a[1]), "r"(a[2]), "r"(a[3]), "r"(b[0]), "r"(b[1]));
}

// ---------------------------------------------------------------------------
// Kernel 0: zero d_out
// ---------------------------------------------------------------------------
__global__ void k_zero(float4* p, size_t n4) {
    size_t i = (size_t)blockIdx.x * blockDim.x + threadIdx.x;
    size_t stride = (size_t)gridDim.x * blockDim.x;
    float4 z = make_float4(0.f, 0.f, 0.f, 0.f);
    for (; i < n4; i += stride) p[i] = z;
}

// ---------------------------------------------------------------------------
// Kernel 1: router scores (exact fp32) — one warp per token
// ---------------------------------------------------------------------------
__global__ void k_router(const float* __restrict__ x, const float* __restrict__ wr,
                         const float* __restrict__ br) {
    int gw   = (blockIdx.x * blockDim.x + threadIdx.x) >> 5;
    int lane = threadIdx.x & 31;
    if (gw >= B_ * L_) return;
    const float4* row = (const float4*)(x + (size_t)gw * D_);
    const float4* w   = (const float4*)wr;
    float acc = 0.f;
    #pragma unroll 4
    for (int i = lane; i < D_ / 4; i += 32) {
        float4 a = row[i], b = w[i];
        acc += a.x * b.x + a.y * b.y + a.z * b.z + a.w * b.w;
    }
    #pragma unroll
    for (int o = 16; o; o >>= 1) acc += __shfl_xor_sync(0xffffffff, acc, o);
    if (lane == 0) g_scores[gw] = acc + br[0];
}

// ---------------------------------------------------------------------------
// Kernel 2: per-batch k-th-largest threshold via SMEM bitonic sort
// ---------------------------------------------------------------------------
__global__ void k_topk() {
    __shared__ float s[L_];
    int b = blockIdx.x, tid = threadIdx.x;
    for (int i = tid; i < L_; i += blockDim.x) s[i] = g_scores[b * L_ + i];
    __syncthreads();
    for (int size = 2; size <= L_; size <<= 1) {
        for (int stride = size >> 1; stride > 0; stride >>= 1) {
            for (int t = tid; t < L_; t += blockDim.x) {
                int p = t ^ stride;
                if (p > t) {
                    bool up = ((t & size) == 0);
                    float a = s[t], c = s[p];
                    if (up ? (a > c) : (a < c)) { s[t] = c; s[p] = a; }
                }
            }
            __syncthreads();
        }
    }
    if (tid == 0) { g_thr[b] = s[L_ - KCAP]; g_cnt[b] = 0; }
}

// ---------------------------------------------------------------------------
// Kernels 3/4: compact selected-index list (order irrelevant for correctness)
// ---------------------------------------------------------------------------
__global__ void k_sel_gt() {
    int i = blockIdx.x * blockDim.x + threadIdx.x;
    if (i >= B_ * L_) return;
    int b = i >> 12;
    if (g_scores[i] > g_thr[b]) {
        int p = atomicAdd(&g_cnt[b], 1);
        g_idx[b * KCAP + p] = i & (L_ - 1);
    }
}
__global__ void k_sel_eq() {
    int i = blockIdx.x * blockDim.x + threadIdx.x;
    if (i >= B_ * L_) return;
    int b = i >> 12;
    if (g_scores[i] == g_thr[b]) {
        int p = atomicAdd(&g_cnt[b], 1);
        if (p < KCAP) g_idx[b * KCAP + p] = i & (L_ - 1);
    }
}

// ---------------------------------------------------------------------------
// Kernel 5: gather selected tokens (+ RNA tf32 rounding for the GEMM)
// ---------------------------------------------------------------------------
__global__ void k_gather(const float* __restrict__ x) {
    int r   = blockIdx.x;
    int b   = r >> 11;
    int tok = g_idx[r];
    const float4* src = (const float4*)(x + ((size_t)(b * L_ + tok)) * D_);
    float4*       dst = (float4*)(g_xsel + (size_t)r * D_);
    for (int i = threadIdx.x; i < D_ / 4; i += blockDim.x) {
        float4 v = src[i];
        v.x = to_tf32(v.x); v.y = to_tf32(v.y); v.z = to_tf32(v.z); v.w = to_tf32(v.w);
        dst[i] = v;
    }
}

// ---------------------------------------------------------------------------
// Kernel 6: transpose weights to K-major (+ RNA tf32 rounding)
// ---------------------------------------------------------------------------
__global__ void k_transpose(const float* __restrict__ src, int R, int C, int which) {
    __shared__ float t[32][33];
    float* dst = which ? g_w2t : g_w1t;
    int c0 = blockIdx.x * 32, r0 = blockIdx.y * 32;
    for (int j = threadIdx.y; j < 32; j += 8)
        t[j][threadIdx.x] = src[(size_t)(r0 + j) * C + c0 + threadIdx.x];
    __syncthreads();
    for (int j = threadIdx.y; j < 32; j += 8)
        dst[(size_t)(c0 + j) * R + r0 + threadIdx.x] = to_tf32(t[threadIdx.x][j]);
}

// ---------------------------------------------------------------------------
// Kernel 7: tf32 mma.sync GEMM   C[M,N] = A[M,K] * Bt[N,K]^T   (+bias epilogue)
//   mode 0: A=g_xsel, Bt=g_w1t, epilogue gelu -> g_h (tf32-rounded)
//   mode 1: A=g_h,    Bt=g_w2t, epilogue bias -> scatter to out via g_idx
// CTA 128x128x32, 128 threads, 4 warps (2x2) each computing 64x64.
// 3-stage cp.async ring, ONE __syncthreads per k-tile. 144B SMEM rows
// (bank-conflict-free scalar LDS). 2 CTAs/SM (110.6KB dyn smem each).
// ---------------------------------------------------------------------------
#define TK 32
#define SROW 36                      // floats per SMEM row (32 data + 4 pad)
#define A_BYTES (128 * SROW * 4)     // 18432
#define STAGE_BYTES (2 * A_BYTES)    // 36864 (A then B)
#define NSTAGE 3
#define SM_TOTAL (NSTAGE * STAGE_BYTES)  // 110592

__device__ __forceinline__ void prefetch_stage(
    uint32_t sb, int stage, const float* __restrict__ A, const float* __restrict__ Bt,
    size_t rowA0, size_t rowB0, int Ktot, int k0, int tid)
{
    uint32_t base = sb + stage * STAGE_BYTES;
    #pragma unroll
    for (int j = 0; j < 8; j++) {
        int c = j * 128 + tid;
        int r = c >> 3, q = c & 7;
        const float* ga = A  + (rowA0 + (size_t)r) * (size_t)Ktot + k0 + q * 4;
        const float* gb = Bt + (rowB0 + (size_t)r) * (size_t)Ktot + k0 + q * 4;
        uint32_t sa = base + (uint32_t)(r * 144 + q * 16);
        uint32_t sbb = sa + A_BYTES;
        asm volatile("cp.async.cg.shared.global [%0], [%1], 16;" :: "r"(sa),  "l"(ga) : "memory");
        asm volatile("cp.async.cg.shared.global [%0], [%1], 16;" :: "r"(sbb), "l"(gb) : "memory");
    }
}

__global__ __launch_bounds__(128) void k_gemm(
    const float* __restrict__ bias, float* __restrict__ out,
    int Ktot, int Ntot, int mode)
{
    extern __shared__ char smem[];
    uint32_t sb = cvta_smem(smem);
    int tid  = threadIdx.x;
    int wid  = tid >> 5;
    int lane = tid & 31;
    int wm   = wid & 1;                       // warp M index (0/1)
    int wn   = wid >> 1;                      // warp N index (0/1)

    const float* A  = (mode == 0) ? g_xsel : g_h;
    const float* Bt = (mode == 0) ? g_w1t  : g_w2t;

    const size_t rowA0 = (size_t)blockIdx.y * 128;
    const size_t colB0 = (size_t)blockIdx.x * 128;
    const int NS = Ktot / TK;

    float acc[4][8][4];
    #pragma unroll
    for (int mi = 0; mi < 4; mi++)
        #pragma unroll
        for (int ni = 0; ni < 8; ni++)
            #pragma unroll
            for (int j = 0; j < 4; j++) acc[mi][ni][j] = 0.f;

    // prologue: stages 0, 1 in flight
    prefetch_stage(sb, 0, A, Bt, rowA0, colB0, Ktot, 0, tid);
    asm volatile("cp.async.commit_group;" ::: "memory");
    prefetch_stage(sb, 1, A, Bt, rowA0, colB0, Ktot, TK, tid);
    asm volatile("cp.async.commit_group;" ::: "memory");

    const int lr = lane >> 2;   // 0..7
    const int lc = lane & 3;    // 0..3

    int buf = 0;                // = s % 3
    for (int s = 0; s < NS; s++) {
        asm volatile("cp.async.wait_group 1;" ::: "memory");
        __syncthreads();        // stage s ready for ALL warps; also: every warp
                                // finished reading buffer (s+2)%3 back at iter s-1

        // refill the ring 2 tiles ahead, BEFORE issuing this tile's MMAs
        if (s + 2 < NS) {
            int nbuf = buf + 2; if (nbuf >= NSTAGE) nbuf -= NSTAGE;
            prefetch_stage(sb, nbuf, A, Bt, rowA0, colB0, Ktot, (s + 2) * TK, tid);
        }
        asm volatile("cp.async.commit_group;" ::: "memory");

        const float* sA = (const float*)(smem + buf * STAGE_BYTES);
        const float* sB = (const float*)(smem + buf * STAGE_BYTES + A_BYTES);

        #pragma unroll
        for (int ks = 0; ks < 4; ks++) {
            int kb = ks * 8;
            uint32_t afr[4][4];
            uint32_t bfr[8][2];
            #pragma unroll
            for (int mi = 0; mi < 4; mi++) {
                int r = wm * 64 + mi * 16 + lr;
                int c = kb + lc;
                afr[mi][0] = __float_as_uint(sA[r * SROW + c]);
                afr[mi][1] = __float_as_uint(sA[(r + 8) * SROW + c]);
                afr[mi][2] = __float_as_uint(sA[r * SROW + c + 4]);
                afr[mi][3] = __float_as_uint(sA[(r + 8) * SROW + c + 4]);
            }
            #pragma unroll
            for (int ni = 0; ni < 8; ni++) {
                int n = wn * 64 + ni * 8 + lr;
                bfr[ni][0] = __float_as_uint(sB[n * SROW + kb + lc]);
                bfr[ni][1] = __float_as_uint(sB[n * SROW + kb + 4 + lc]);
            }
            #pragma unroll
            for (int mi = 0; mi < 4; mi++)
                #pragma unroll
                for (int ni = 0; ni < 8; ni++)
                    mma1688(acc[mi][ni], afr[mi], bfr[ni]);
        }

        buf++; if (buf >= NSTAGE) buf -= NSTAGE;
    }

    // ------------------------- epilogue -------------------------
    // accum layout m16n8: c0/c1 at (row lr, col 2*lc / 2*lc+1), c2/c3 at row lr+8
    #pragma unroll
    for (int mi = 0; mi < 4; mi++) {
        size_t m0 = rowA0 + (size_t)(wm * 64 + mi * 16 + lr);
        size_t m1 = m0 + 8;
        if (mode == 0) {
            float* row0 = g_h + m0 * (size_t)Ntot;
            float* row1 = g_h + m1 * (size_t)Ntot;
            #pragma unroll
            for (int ni = 0; ni < 8; ni++) {
                size_t col = colB0 + wn * 64 + ni * 8 + lc * 2;
                float b0 = bias[col], b1 = bias[col + 1];
                float2 v0, v1;
                v0.x = to_tf32(gelu_tanh(acc[mi][ni][0] + b0));
                v0.y = to_tf32(gelu_tanh(acc[mi][ni][1] + b1));
                v1.x = to_tf32(gelu_tanh(acc[mi][ni][2] + b0));
                v1.y = to_tf32(gelu_tanh(acc[mi][ni][3] + b1));
                *(float2*)(row0 + col) = v0;
                *(float2*)(row1 + col) = v1;
            }
        } else {
            int tok0 = g_idx[m0], tok1 = g_idx[m1];
            int b0i = (int)(m0 >> 11), b1i = (int)(m1 >> 11);
            float* row0 = out + ((size_t)(b0i * L_ + tok0)) * D_;
            float* row1 = out + ((size_t)(b1i * L_ + tok1)) * D_;
            #pragma unroll
            for (int ni = 0; ni < 8; ni++) {
                size_t col = colB0 + wn * 64 + ni * 8 + lc * 2;
                float b0 = bias[col], b1 = bias[col + 1];
                float2 v0, v1;
                v0.x = acc[mi][ni][0] + b0;
                v0.y = acc[mi][ni][1] + b1;
                v1.x = acc[mi][ni][2] + b0;
                v1.y = acc[mi][ni][3] + b1;
                *(float2*)(row0 + col) = v0;
                *(float2*)(row1 + col) = v1;
            }
        }
    }
}

// ---------------------------------------------------------------------------
// Host entry
// ---------------------------------------------------------------------------
extern "C" void kernel_launch(void* const* d_in, const int* in_sizes, int n_in,
                              void* d_out, int out_size) {
    (void)in_sizes; (void)n_in;
    const float* x  = (const float*)d_in[0];
    const float* wr = (const float*)d_in[1];
    const float* br = (const float*)d_in[2];
    const float* w1 = (const float*)d_in[3];
    const float* b1 = (const float*)d_in[4];
    const float* w2 = (const float*)d_in[5];
    const float* b2 = (const float*)d_in[6];
    float* out = (float*)d_out;

    // 0) zero output (poisoned by harness)
    k_zero<<<2048, 256>>>((float4*)out, (size_t)out_size / 4);

    // 1) router scores (fp32 exact)
    k_router<<<(B_ * L_ * 32) / 256, 256>>>(x, wr, br);

    // 2) per-batch threshold + counter reset
    k_topk<<<B_, 1024>>>();

    // 3/4) selection -> compact index list
    k_sel_gt<<<(B_ * L_) / 256, 256>>>();
    k_sel_eq<<<(B_ * L_) / 256, 256>>>();

    // 5) gather selected tokens (tf32-rounded)
    k_gather<<<BK, 256>>>(x);

    // 6) transpose weights to K-major (tf32-rounded)
    dim3 tb(32, 8);
    k_transpose<<<dim3(DF_ / 32, D_ / 32), tb>>>(w1, D_, DF_, 0);   // -> g_w1t [DF,D]
    k_transpose<<<dim3(D_ / 32, DF_ / 32), tb>>>(w2, DF_, D_, 1);   // -> g_w2t [D,DF]

    // 7) FFN GEMMs (mma.sync tf32, 3-stage cp.async ring)
    static int smem_set = 0;
    if (!smem_set) {
        cudaFuncSetAttribute(k_gemm, cudaFuncAttributeMaxDynamicSharedMemorySize, SM_TOTAL);
        smem_set = 1;
    }
    k_gemm<<<dim3(DF_ / 128, BK / 128), 128, SM_TOTAL>>>(b1, out, D_,  DF_, 0);
    k_gemm<<<dim3(D_  / 128, BK / 128), 128, SM_TOTAL>>>(b2, out, DF_, D_,  1);
}